// round 1
// baseline (speedup 1.0000x reference)
#include <cuda_runtime.h>
#include <cstdint>

// Problem constants (match reference)
#define B     32
#define TMAX  512
#define D     384
#define MAXDUR 8
#define TOUT  (TMAX * (MAXDUR - 1))   // 3584
#define VEC   (D / 4)                 // 96 float4 per row

// Scratch: frame -> token index per batch; -1 = padded frame.
// 32 * 3584 * 4 B = 448 KB, static __device__ (no allocation).
__device__ int g_idx[B * TOUT];

// Kernel 1: one CTA per batch row. 512 threads = TMAX tokens.
// Computes masked durations, all-zero fallback, inclusive scan,
// then scatters token ids into g_idx and -1 into the padded tail.
__global__ void __launch_bounds__(TMAX) build_idx_kernel(
    const int* __restrict__ ds,     // [B, TMAX]
    const int* __restrict__ ilens,  // [B]
    int* __restrict__ idx_out)      // [B, TOUT]
{
    const int b = blockIdx.x;
    const int t = threadIdx.x;

    __shared__ int s[TMAX];

    const int L = ilens[b];
    int d = (t < L) ? ds[b * TMAX + t] : 0;
    s[t] = d;
    __syncthreads();

    // Hillis-Steele inclusive scan over 512 elements
    #pragma unroll
    for (int off = 1; off < TMAX; off <<= 1) {
        int v = (t >= off) ? s[t - off] : 0;
        __syncthreads();
        s[t] += v;
        __syncthreads();
    }

    int total = s[TMAX - 1];
    int cum;
    if (total == 0) {
        // all-zero fallback: d = mask  ->  cum[t] = min(t+1, L)
        d   = (t < L) ? 1 : 0;
        cum = (t < L) ? (t + 1) : L;
        total = L;   // L >= 1 guaranteed by the reference
    } else {
        cum = s[t];
    }

    // Scatter: token t owns frames [cum-d, cum)
    const int start = cum - d;
    int* row = idx_out + b * TOUT;
    for (int f = start; f < cum; ++f) {
        if (f < TOUT) row[f] = t;
    }

    // Padded tail: frames [total, TOUT) -> -1
    for (int f = total + t; f < TOUT; f += TMAX) {
        row[f] = -1;
    }
}

// Kernel 2: flat float4 gather. One thread per 16B output chunk.
// N = B * TOUT * VEC = 11,010,048 threads.
__global__ void __launch_bounds__(256) gather_kernel(
    const float4* __restrict__ xs,   // [B, TMAX, VEC]
    const int*    __restrict__ idx,  // [B, TOUT]
    float4*       __restrict__ out)  // [B, TOUT, VEC]
{
    const int e = blockIdx.x * blockDim.x + threadIdx.x;
    const int N = B * TOUT * VEC;
    if (e >= N) return;

    const int row = e / VEC;          // b * TOUT + f
    const int v   = e - row * VEC;
    const int b   = row / TOUT;

    const int i = __ldg(idx + row);

    float4 r = make_float4(0.f, 0.f, 0.f, 0.f);
    if (i >= 0) {
        r = __ldg(xs + ((long)b * TMAX + i) * VEC + v);
    }
    out[e] = r;
}

extern "C" void kernel_launch(void* const* d_in, const int* in_sizes, int n_in,
                              void* d_out, int out_size)
{
    const float* xs    = (const float*)d_in[0];  // [B, TMAX, D] fp32
    const int*   ds    = (const int*)  d_in[1];  // [B, TMAX] int32
    const int*   ilens = (const int*)  d_in[2];  // [B] int32
    float*       out   = (float*)d_out;          // [B, TOUT, D] fp32

    int* idx_ptr = nullptr;
    cudaGetSymbolAddress((void**)&idx_ptr, g_idx);

    build_idx_kernel<<<B, TMAX>>>(ds, ilens, idx_ptr);

    const int N = B * TOUT * VEC;                // 11,010,048
    const int threads = 256;
    const int blocks  = (N + threads - 1) / threads;
    gather_kernel<<<blocks, threads>>>(
        (const float4*)xs, idx_ptr, (float4*)out);
}

// round 2
// speedup vs baseline: 1.2222x; 1.2222x over previous
#include <cuda_runtime.h>
#include <cstdint>

// Problem constants (match reference)
#define B      32
#define TMAX   512
#define D      384
#define MAXDUR 8
#define TOUT   (TMAX * (MAXDUR - 1))   // 3584
#define VEC    (D / 4)                 // 96 float4 per row
#define NROWS  (B * TOUT)              // 114688 output rows

// Scratch: frame -> token index per batch; -1 = padded frame. 448 KB static.
__device__ int g_idx[NROWS];

// ---------------------------------------------------------------------------
// Kernel 1: one CTA per batch row, 512 threads = TMAX tokens.
// shfl warp scan + cross-warp scan (2 barriers instead of 18), then scatter
// token ids into g_idx, -1 into padded tail.
// ---------------------------------------------------------------------------
__global__ void __launch_bounds__(TMAX) build_idx_kernel(
    const int* __restrict__ ds,     // [B, TMAX]
    const int* __restrict__ ilens,  // [B]
    int* __restrict__ idx_out)      // [B, TOUT]
{
    const int b    = blockIdx.x;
    const int t    = threadIdx.x;
    const int lane = t & 31;
    const int wid  = t >> 5;        // 0..15

    __shared__ int s_wsum[16];

    const int L = ilens[b];
    int d = (t < L) ? ds[b * TMAX + t] : 0;

    // warp inclusive scan
    int cum = d;
    #pragma unroll
    for (int off = 1; off < 32; off <<= 1) {
        int v = __shfl_up_sync(0xffffffffu, cum, off);
        if (lane >= off) cum += v;
    }
    if (lane == 31) s_wsum[wid] = cum;
    __syncthreads();

    // warp 0 scans the 16 warp sums (inclusive), write back
    if (wid == 0 && lane < 16) {
        int v = s_wsum[lane];
        #pragma unroll
        for (int off = 1; off < 16; off <<= 1) {
            int u = __shfl_up_sync(0x0000ffffu, v, off);
            if (lane >= off) v += u;
        }
        s_wsum[lane] = v;
    }
    __syncthreads();

    cum += (wid > 0) ? s_wsum[wid - 1] : 0;
    int total = s_wsum[15];

    if (total == 0) {
        // all-zero fallback: d = mask  ->  cum[t] = min(t+1, L)
        d     = (t < L) ? 1 : 0;
        cum   = (t < L) ? (t + 1) : L;
        total = L;   // L >= 1 guaranteed
    }

    // Scatter: token t owns frames [cum-d, cum)
    int* row = idx_out + b * TOUT;
    const int start = cum - d;
    for (int f = start; f < cum; ++f) {
        if (f < TOUT) row[f] = t;
    }

    // Padded tail: frames [total, TOUT) -> -1
    for (int f = total + t; f < TOUT; f += TMAX) {
        row[f] = -1;
    }
}

// ---------------------------------------------------------------------------
// Kernel 2: warp-per-row gather. Lane l covers float4 v = {l, l+32, l+64}.
// idx load is warp-uniform; 3 independent loads + 3 independent stores per
// thread -> MLP 3. No div-by-96.
// ---------------------------------------------------------------------------
__global__ void __launch_bounds__(256) gather_kernel(
    const float4* __restrict__ xs,   // [B, TMAX, VEC]
    const int*    __restrict__ idx,  // [NROWS]
    float4*       __restrict__ out)  // [NROWS, VEC]
{
    const int gt   = blockIdx.x * blockDim.x + threadIdx.x;
    const int row  = gt >> 5;        // global warp id == output row
    const int lane = gt & 31;
    if (row >= NROWS) return;

    const int b = row / TOUT;        // mul-shift
    const int i = __ldg(idx + row);  // warp-uniform

    float4* dst = out + (long)row * VEC;

    if (i >= 0) {
        const float4* src = xs + ((long)b * TMAX + i) * VEC;
        float4 r0 = __ldg(src + lane);
        float4 r1 = __ldg(src + lane + 32);
        float4 r2 = __ldg(src + lane + 64);
        dst[lane]      = r0;
        dst[lane + 32] = r1;
        dst[lane + 64] = r2;
    } else {
        const float4 z = make_float4(0.f, 0.f, 0.f, 0.f);
        dst[lane]      = z;
        dst[lane + 32] = z;
        dst[lane + 64] = z;
    }
}

extern "C" void kernel_launch(void* const* d_in, const int* in_sizes, int n_in,
                              void* d_out, int out_size)
{
    const float* xs    = (const float*)d_in[0];  // [B, TMAX, D] fp32
    const int*   ds    = (const int*)  d_in[1];  // [B, TMAX] int32
    const int*   ilens = (const int*)  d_in[2];  // [B] int32
    float*       out   = (float*)d_out;          // [B, TOUT, D] fp32

    int* idx_ptr = nullptr;
    cudaGetSymbolAddress((void**)&idx_ptr, g_idx);

    build_idx_kernel<<<B, TMAX>>>(ds, ilens, idx_ptr);

    // NROWS warps total, 8 warps per 256-thread CTA
    const int blocks = (NROWS * 32) / 256;      // 14336
    gather_kernel<<<blocks, 256>>>(
        (const float4*)xs, idx_ptr, (float4*)out);
}

// round 4
// speedup vs baseline: 1.5304x; 1.2522x over previous
#include <cuda_runtime.h>
#include <cstdint>

// Problem constants (match reference)
#define B      32
#define TMAX   512
#define D      384
#define MAXDUR 8
#define TOUT   (TMAX * (MAXDUR - 1))   // 3584
#define VEC    (D / 4)                 // 96 float4 per row
#define ROWS_PER_CTA 8                 // 8 warps, 1 output row each
#define CTAS_PER_B   (TOUT / ROWS_PER_CTA)   // 448
#define NCTAS  (B * CTAS_PER_B)        // 14336

// ---------------------------------------------------------------------------
// Single fused kernel. Each CTA (256 thr = 8 warps):
//   1. loads its batch's 512 durations, masks by ilen, block-scans to smem cum
//   2. all-zero fallback (cum[t] = min(t+1, L))
//   3. each warp binary-searches its output frame f in cum (searchsorted right,
//      10 steps: insertion point range [0,512] needs ceil(log2(513)) = 10)
//   4. warp gathers 96 float4 of xs[b, idx, :] -> out row (streaming stores)
// ---------------------------------------------------------------------------
__global__ void __launch_bounds__(256) lenreg_fused_kernel(
    const float4* __restrict__ xs,     // [B, TMAX, VEC]
    const int*    __restrict__ ds,     // [B, TMAX]
    const int*    __restrict__ ilens,  // [B]
    float4*       __restrict__ out)    // [B, TOUT, VEC]
{
    const int cta    = blockIdx.x;
    const int b      = cta / CTAS_PER_B;              // mul-shift
    const int f_base = (cta - b * CTAS_PER_B) * ROWS_PER_CTA;

    const int t    = threadIdx.x;     // 0..255
    const int lane = t & 31;
    const int wid  = t >> 5;          // 0..7

    __shared__ int s_cum[TMAX];       // inclusive cumsum of masked durations
    __shared__ int s_wsum[8];

    const int L = ilens[b];

    // --- block scan: thread t owns elements 2t, 2t+1 --------------------
    const int e0 = 2 * t;
    const int e1 = 2 * t + 1;
    int d0 = (e0 < L) ? __ldg(ds + b * TMAX + e0) : 0;
    int d1 = (e1 < L) ? __ldg(ds + b * TMAX + e1) : 0;
    int pair = d0 + d1;

    // warp inclusive scan of pair sums
    int p = pair;
    #pragma unroll
    for (int off = 1; off < 32; off <<= 1) {
        int v = __shfl_up_sync(0xffffffffu, p, off);
        if (lane >= off) p += v;
    }
    if (lane == 31) s_wsum[wid] = p;
    __syncthreads();

    // cross-warp exclusive offset (8 values, scanned redundantly per thread)
    int woff = 0;
    #pragma unroll
    for (int w = 0; w < 8; ++w)
        woff += (w < wid) ? s_wsum[w] : 0;

    const int excl = p - pair + woff;     // exclusive prefix before e0
    s_cum[e0] = excl + d0;
    s_cum[e1] = excl + d0 + d1;
    __syncthreads();

    int total = s_cum[TMAX - 1];

    if (total == 0) {
        // all-zero fallback: d = mask -> cum[t'] = min(t'+1, L)
        s_cum[e0] = (e0 < L) ? (e0 + 1) : L;
        s_cum[e1] = (e1 < L) ? (e1 + 1) : L;
        total = L;                         // L >= 1 guaranteed
        __syncthreads();
    }

    // --- per-warp: binary search + gather --------------------------------
    const int f = f_base + wid;            // this warp's output frame

    // searchsorted(cum, f, side='right'): first idx with cum[idx] > f.
    // 10 iterations to fully collapse [0, 512] insertion range.
    int lo = 0, hi = TMAX;
    #pragma unroll
    for (int step = 0; step < 10; ++step) {
        int mid = (lo + hi) >> 1;
        if (s_cum[mid] <= f) lo = mid + 1; else hi = mid;
    }
    int idx = (lo < TMAX - 1) ? lo : (TMAX - 1);

    float4* dst = out + ((long)b * TOUT + f) * VEC;

    if (f < total) {
        const float4* src = xs + ((long)b * TMAX + idx) * VEC;
        float4 r0 = __ldg(src + lane);
        float4 r1 = __ldg(src + lane + 32);
        float4 r2 = __ldg(src + lane + 64);
        __stcs(dst + lane,      r0);
        __stcs(dst + lane + 32, r1);
        __stcs(dst + lane + 64, r2);
    } else {
        const float4 z = make_float4(0.f, 0.f, 0.f, 0.f);
        __stcs(dst + lane,      z);
        __stcs(dst + lane + 32, z);
        __stcs(dst + lane + 64, z);
    }
}

extern "C" void kernel_launch(void* const* d_in, const int* in_sizes, int n_in,
                              void* d_out, int out_size)
{
    const float* xs    = (const float*)d_in[0];  // [B, TMAX, D] fp32
    const int*   ds    = (const int*)  d_in[1];  // [B, TMAX] int32
    const int*   ilens = (const int*)  d_in[2];  // [B] int32
    float*       out   = (float*)d_out;          // [B, TOUT, D] fp32

    lenreg_fused_kernel<<<NCTAS, 256>>>(
        (const float4*)xs, ds, ilens, (float4*)out);
}